// round 1
// baseline (speedup 1.0000x reference)
#include <cuda_runtime.h>

// Problem constants
#define N_VOXELS   32768
#define N_CODES    8192
#define DIM        64
#define Q_ELEMS    (N_VOXELS * DIM)      // 2097152
#define OFF_VQ     (Q_ELEMS)             // vq_loss scalar
#define OFF_COMMIT (Q_ELEMS + 1)         // commitment_loss scalar
#define OFF_IDX    (Q_ELEMS + 2)         // indices [N_VOXELS]

#define TC          64                   // codes per smem tile
#define MAIN_THREADS 128
#define MAIN_BLOCKS (N_VOXELS / MAIN_THREADS)   // 256

// Scratch (allocation-free rule: __device__ globals)
__device__ float g_esq[N_CODES];
__device__ float g_partial[MAIN_BLOCKS];

// ---- packed f32x2 helpers (Blackwell FFMA2 path, PTX-only) ----
__device__ __forceinline__ unsigned long long ffma2(unsigned long long a,
                                                    unsigned long long b,
                                                    unsigned long long c) {
    unsigned long long d;
    asm("fma.rn.f32x2 %0, %1, %2, %3;" : "=l"(d) : "l"(a), "l"(b), "l"(c));
    return d;
}
__device__ __forceinline__ float2 unpack2(unsigned long long v) {
    float2 r;
    asm("mov.b64 {%0, %1}, %2;" : "=f"(r.x), "=f"(r.y) : "l"(v));
    return r;
}

// ---- kernel 0: ||e||^2 per code ----
__global__ void esq_kernel(const float* __restrict__ emb) {
    int c = blockIdx.x * blockDim.x + threadIdx.x;
    if (c < N_CODES) {
        const float4* row = reinterpret_cast<const float4*>(emb + (size_t)c * DIM);
        float s = 0.f;
#pragma unroll
        for (int i = 0; i < DIM / 4; i++) {
            float4 v = row[i];
            s += v.x * v.x + v.y * v.y + v.z * v.z + v.w * v.w;
        }
        g_esq[c] = s;
    }
}

// ---- kernel 1: main distance / argmin / gather / partial loss ----
__global__ void __launch_bounds__(MAIN_THREADS, 4)
vq_main_kernel(const float* __restrict__ z, const float* __restrict__ emb,
               float* __restrict__ out) {
    __shared__ __align__(16) unsigned long long s_code[TC * DIM / 2];  // 16 KB
    __shared__ float s_esq[TC];
    __shared__ float s_red[MAIN_THREADS];

    const int v = blockIdx.x * MAIN_THREADS + threadIdx.x;

    // z row -> 32 packed f32x2 registers
    unsigned long long zr[DIM / 2];
    {
        const ulonglong2* zp = reinterpret_cast<const ulonglong2*>(z + (size_t)v * DIM);
#pragma unroll
        for (int i = 0; i < DIM / 4; i++) {
            ulonglong2 t = zp[i];
            zr[2 * i]     = t.x;
            zr[2 * i + 1] = t.y;
        }
    }

    float best = 3.4e38f;
    int   bidx = 0;

    for (int t = 0; t < N_CODES / TC; t++) {
        __syncthreads();
        {
            const ulonglong2* ep =
                reinterpret_cast<const ulonglong2*>(emb + (size_t)t * TC * DIM);
            ulonglong2* sp = reinterpret_cast<ulonglong2*>(s_code);
#pragma unroll
            for (int i = threadIdx.x; i < TC * DIM / 4; i += MAIN_THREADS)
                sp[i] = ep[i];
            if (threadIdx.x < TC) s_esq[threadIdx.x] = g_esq[t * TC + threadIdx.x];
        }
        __syncthreads();

#pragma unroll 2
        for (int c = 0; c < TC; c++) {
            const ulonglong2* crow =
                reinterpret_cast<const ulonglong2*>(s_code + c * (DIM / 2));
            unsigned long long a0 = 0ull, a1 = 0ull, a2 = 0ull, a3 = 0ull;
#pragma unroll
            for (int j = 0; j < DIM / 4; j += 2) {
                ulonglong2 c0 = crow[j];
                ulonglong2 c1 = crow[j + 1];
                a0 = ffma2(zr[2 * j],     c0.x, a0);
                a1 = ffma2(zr[2 * j + 1], c0.y, a1);
                a2 = ffma2(zr[2 * j + 2], c1.x, a2);
                a3 = ffma2(zr[2 * j + 3], c1.y, a3);
            }
            float2 f0 = unpack2(a0), f1 = unpack2(a1);
            float2 f2 = unpack2(a2), f3 = unpack2(a3);
            float dot = ((f0.x + f0.y) + (f1.x + f1.y)) +
                        ((f2.x + f2.y) + (f3.x + f3.y));
            float score = fmaf(-2.f, dot, s_esq[c]);
            if (score < best) {  // strict '<' == first-index tie-break (argmin)
                best = score;
                bidx = t * TC + c;
            }
        }
    }

    // epilogue: gather winning code, straight-through output, local loss
    float lsum = 0.f;
    {
        const float4* qp = reinterpret_cast<const float4*>(emb + (size_t)bidx * DIM);
        float4* qo = reinterpret_cast<float4*>(out + (size_t)v * DIM);
#pragma unroll
        for (int i = 0; i < DIM / 4; i++) {
            float4 q  = qp[i];
            float2 z0 = unpack2(zr[2 * i]);
            float2 z1 = unpack2(zr[2 * i + 1]);
            float dx = q.x - z0.x, dy = q.y - z0.y;
            float dz = q.z - z1.x, dw = q.w - z1.y;
            // quantized_st = z + (q - z) (mimic reference rounding)
            qo[i] = make_float4(z0.x + dx, z0.y + dy, z1.x + dz, z1.y + dw);
            lsum += dx * dx + dy * dy + dz * dz + dw * dw;
        }
    }
    out[OFF_IDX + v] = (float)bidx;

    // deterministic block tree reduction
    s_red[threadIdx.x] = lsum;
    __syncthreads();
#pragma unroll
    for (int o = MAIN_THREADS / 2; o > 0; o >>= 1) {
        if (threadIdx.x < o) s_red[threadIdx.x] += s_red[threadIdx.x + o];
        __syncthreads();
    }
    if (threadIdx.x == 0) g_partial[blockIdx.x] = s_red[0];
}

// ---- kernel 2: fixed-order final reduction, write both loss scalars ----
__global__ void final_kernel(float* __restrict__ out) {
    __shared__ float s[MAIN_BLOCKS];
    int tid = threadIdx.x;
    s[tid] = g_partial[tid];
    __syncthreads();
#pragma unroll
    for (int o = MAIN_BLOCKS / 2; o > 0; o >>= 1) {
        if (tid < o) s[tid] += s[tid + o];
        __syncthreads();
    }
    if (tid == 0) {
        float loss = s[0] / (float)Q_ELEMS;  // mean((z - q)^2)
        out[OFF_VQ]     = loss;  // vq_loss
        out[OFF_COMMIT] = loss;  // commitment_loss (numerically identical)
    }
}

extern "C" void kernel_launch(void* const* d_in, const int* in_sizes, int n_in,
                              void* d_out, int out_size) {
    const float* z   = (const float*)d_in[0];
    const float* emb = (const float*)d_in[1];
    if (n_in >= 2 && in_sizes[0] < in_sizes[1]) {  // z_feats is the larger tensor
        const float* tmp = z; z = emb; emb = tmp;
    }
    float* out = (float*)d_out;

    esq_kernel<<<(N_CODES + 255) / 256, 256>>>(emb);
    vq_main_kernel<<<MAIN_BLOCKS, MAIN_THREADS>>>(z, emb, out);
    final_kernel<<<1, MAIN_BLOCKS>>>(out);
}

// round 3
// speedup vs baseline: 1.2552x; 1.2552x over previous
#include <cuda_runtime.h>
#include <cuda_fp16.h>
#include <cstdint>

// ---------------- problem constants ----------------
#define NV 32768
#define NC 8192
#define DIM 64
#define Q_ELEMS (NV * DIM)
#define OFF_VQ Q_ELEMS
#define OFF_COMMIT (Q_ELEMS + 1)
#define OFF_IDX (Q_ELEMS + 2)

#define KC 192          // concatenated K: [zh|zh|zl] x [eh|el|eh]
#define KP_BYTES 400    // padded smem row stride (25 x 16B, conflict-free)
#define TILE_M 128
#define TILE_N 64
#define NT (NC / TILE_N)        // 128 tiles
#define M_BLOCKS (NV / TILE_M)  // 256 CTAs
#define TAU 5e-3f

// dynamic smem: A 128*400=51200 | B stage0 64*400=25600 | B stage1 | esq 2*256
#define SM_A 0
#define SM_B 51200
#define SM_BSTRIDE 25600
#define SM_ESQ 102400
#define DYN_SMEM 102912

// ---------------- device scratch ----------------
__device__ __align__(16) __half g_zcat[NV * KC];   // 12 MB
__device__ __align__(16) __half g_ecat[NC * KC];   // 3 MB
__device__ __align__(16) float g_esq[NC];
__device__ int g_bidx[NV];
__device__ int g_list[NV];
__device__ int g_count;
__device__ float g_partial[M_BLOCKS];

// ---------------- PTX helpers (baseline sm_80+ features only) ----------------
__device__ __forceinline__ uint32_t smem_u32(const void* p) {
    uint32_t a;
    asm("{ .reg .u64 t; cvta.to.shared.u64 t, %1; cvt.u32.u64 %0, t; }" : "=r"(a) : "l"(p));
    return a;
}
__device__ __forceinline__ void cpa16(uint32_t dst, const void* src) {
    asm volatile("cp.async.cg.shared.global [%0], [%1], 16;" :: "r"(dst), "l"(src));
}
#define CP_COMMIT() asm volatile("cp.async.commit_group;" ::: "memory")
#define CP_WAIT(n) asm volatile("cp.async.wait_group %0;" :: "n"(n) : "memory")

__device__ __forceinline__ void ldsm4(uint32_t& r0, uint32_t& r1, uint32_t& r2,
                                      uint32_t& r3, uint32_t addr) {
    asm volatile("ldmatrix.sync.aligned.m8n8.x4.shared.b16 {%0,%1,%2,%3}, [%4];"
                 : "=r"(r0), "=r"(r1), "=r"(r2), "=r"(r3) : "r"(addr));
}
__device__ __forceinline__ void mma16816(float* c, const uint32_t* a, uint32_t b0,
                                         uint32_t b1) {
    asm volatile(
        "mma.sync.aligned.m16n8k16.row.col.f32.f16.f16.f32 "
        "{%0,%1,%2,%3}, {%4,%5,%6,%7}, {%8,%9}, {%0,%1,%2,%3};"
        : "+f"(c[0]), "+f"(c[1]), "+f"(c[2]), "+f"(c[3])
        : "r"(a[0]), "r"(a[1]), "r"(a[2]), "r"(a[3]), "r"(b0), "r"(b1));
}

// ---------------- prep: codebook -> fp16 split concat + exact esq ----------------
__global__ void prep_emb_kernel(const float* __restrict__ emb) {
    int c = blockIdx.x * blockDim.x + threadIdx.x;
    if (c == 0) g_count = 0;
    if (c >= NC) return;
    const float4* row = reinterpret_cast<const float4*>(emb + (size_t)c * DIM);
    __half2* dst = reinterpret_cast<__half2*>(g_ecat + (size_t)c * KC);
    float s = 0.f;
#pragma unroll
    for (int i = 0; i < 16; i++) {
        float4 v = row[i];
        s += v.x * v.x + v.y * v.y + v.z * v.z + v.w * v.w;
        __half hx = __float2half_rn(v.x), hy = __float2half_rn(v.y);
        __half hz = __float2half_rn(v.z), hw = __float2half_rn(v.w);
        __half2 h0 = __halves2half2(hx, hy), h1 = __halves2half2(hz, hw);
        __half2 l0 = __halves2half2(__float2half_rn(v.x - __half2float(hx)),
                                    __float2half_rn(v.y - __half2float(hy)));
        __half2 l1 = __halves2half2(__float2half_rn(v.z - __half2float(hz)),
                                    __float2half_rn(v.w - __half2float(hw)));
        dst[2 * i] = h0;                 // eh   cols [0,64)
        dst[2 * i + 1] = h1;
        dst[32 + 2 * i] = l0;            // el   cols [64,128)
        dst[32 + 2 * i + 1] = l1;
        dst[64 + 2 * i] = h0;            // eh   cols [128,192)
        dst[64 + 2 * i + 1] = h1;
    }
    g_esq[c] = s;
}

// ---------------- prep: z -> fp16 split concat ----------------
__global__ void prep_z_kernel(const float* __restrict__ z) {
    int v = blockIdx.x * blockDim.x + threadIdx.x;
    if (v >= NV) return;
    const float4* row = reinterpret_cast<const float4*>(z + (size_t)v * DIM);
    __half2* dst = reinterpret_cast<__half2*>(g_zcat + (size_t)v * KC);
#pragma unroll
    for (int i = 0; i < 16; i++) {
        float4 vv = row[i];
        __half hx = __float2half_rn(vv.x), hy = __float2half_rn(vv.y);
        __half hz = __float2half_rn(vv.z), hw = __float2half_rn(vv.w);
        __half2 h0 = __halves2half2(hx, hy), h1 = __halves2half2(hz, hw);
        __half2 l0 = __halves2half2(__float2half_rn(vv.x - __half2float(hx)),
                                    __float2half_rn(vv.y - __half2float(hy)));
        __half2 l1 = __halves2half2(__float2half_rn(vv.z - __half2float(hz)),
                                    __float2half_rn(vv.w - __half2float(hw)));
        dst[2 * i] = h0;                 // zh
        dst[2 * i + 1] = h1;
        dst[32 + 2 * i] = h0;            // zh (paired with el)
        dst[32 + 2 * i + 1] = h1;
        dst[64 + 2 * i] = l0;            // zl (paired with eh)
        dst[64 + 2 * i + 1] = l1;
    }
}

// ---------------- main: HMMA distance GEMM + approx argmin ----------------
__global__ void __launch_bounds__(256, 2) vq_mma_kernel() {
    extern __shared__ __align__(16) char dsm[];
    __shared__ float s_b[2][TILE_M], s_b2[2][TILE_M];
    __shared__ int s_i[2][TILE_M];

    const int tid = threadIdx.x;
    const int lane = tid & 31, wid = tid >> 5;
    const int wm = wid & 3, wn = wid >> 2;  // 4 M-stripes x 2 N-stripes
    const uint32_t sb = smem_u32(dsm);

    // A tile: 128 rows x 192 halfs (384B) -> padded 400B rows
    {
        const uint4* asrc =
            reinterpret_cast<const uint4*>(g_zcat + (size_t)blockIdx.x * TILE_M * KC);
#pragma unroll
        for (int i = 0; i < 12; i++) {
            int ch = tid + i * 256;              // 3072 chunks of 16B
            int r = ch / 24, c = ch % 24;
            cpa16(sb + SM_A + r * KP_BYTES + c * 16, asrc + ch);
        }
    }
    // B tile 0 + esq 0
    auto loadB = [&](int t) {
        uint32_t Bs = sb + SM_B + (t & 1) * SM_BSTRIDE;
        const uint4* bsrc =
            reinterpret_cast<const uint4*>(g_ecat + (size_t)t * TILE_N * KC);
#pragma unroll
        for (int i = 0; i < 6; i++) {
            int ch = tid + i * 256;              // 1536 chunks
            int r = ch / 24, c = ch % 24;
            cpa16(Bs + r * KP_BYTES + c * 16, bsrc + ch);
        }
        if (tid < 16)
            cpa16(sb + SM_ESQ + (t & 1) * 256 + tid * 16,
                  reinterpret_cast<const uint4*>(g_esq + t * TILE_N) + tid);
    };
    loadB(0);
    CP_COMMIT();

    float best[4], best2[4];
    int bi[4];
#pragma unroll
    for (int s = 0; s < 4; s++) { best[s] = 3.4e38f; best2[s] = 3.4e38f; bi[s] = 0; }

    // ldmatrix lane addressing (constant parts)
    const uint32_t a_row = wm * 32 + (lane & 15);
    const uint32_t a_koff = (lane >> 4) * 8;
    const uint32_t b_row0 = wn * 32 + ((lane >> 4) * 8) + (lane & 7);
    const uint32_t b_koff = ((lane >> 3) & 1) * 8;

    for (int t = 0; t < NT; t++) {
        if (t + 1 < NT) { loadB(t + 1); CP_COMMIT(); CP_WAIT(1); }
        else           { CP_WAIT(0); }
        __syncthreads();

        float acc[2][4][4];
#pragma unroll
        for (int mf = 0; mf < 2; mf++)
#pragma unroll
            for (int nf = 0; nf < 4; nf++)
#pragma unroll
                for (int e = 0; e < 4; e++) acc[mf][nf][e] = 0.f;

        const uint32_t Bs = sb + SM_B + (t & 1) * SM_BSTRIDE;
#pragma unroll
        for (int ks = 0; ks < KC / 16; ks++) {
            uint32_t a[2][4];
#pragma unroll
            for (int mf = 0; mf < 2; mf++)
                ldsm4(a[mf][0], a[mf][1], a[mf][2], a[mf][3],
                      sb + SM_A + (a_row + mf * 16) * KP_BYTES +
                          (ks * 16 + a_koff) * 2);
            uint32_t b[4][2];
#pragma unroll
            for (int nh = 0; nh < 2; nh++)
                ldsm4(b[2 * nh][0], b[2 * nh][1], b[2 * nh + 1][0], b[2 * nh + 1][1],
                      Bs + (b_row0 + nh * 16) * KP_BYTES + (ks * 16 + b_koff) * 2);
#pragma unroll
            for (int mf = 0; mf < 2; mf++)
#pragma unroll
                for (int nf = 0; nf < 4; nf++)
                    mma16816(acc[mf][nf], a[mf], b[nf][0], b[nf][1]);
        }

        // epilogue: score = esq - 2*dot, track best/best2 per owned row
        const float* esq =
            reinterpret_cast<const float*>(dsm + SM_ESQ + (t & 1) * 256);
        const int nq = (lane & 3) * 2;
#pragma unroll
        for (int mf = 0; mf < 2; mf++) {
#pragma unroll
            for (int nf = 0; nf < 4; nf++) {
                const int n0 = wn * 32 + nf * 8 + nq;
                const float e0 = esq[n0], e1 = esq[n0 + 1];
#pragma unroll
                for (int h = 0; h < 2; h++) {  // row-half: c0,c1 vs c2,c3
                    const int slot = mf * 2 + h;
                    float s0 = fmaf(-2.f, acc[mf][nf][2 * h], e0);
                    float s1 = fmaf(-2.f, acc[mf][nf][2 * h + 1], e1);
                    int i0 = t * TILE_N + n0, i1 = i0 + 1;
                    if (s0 < best[slot]) { best2[slot] = best[slot]; best[slot] = s0; bi[slot] = i0; }
                    else if (s0 < best2[slot]) best2[slot] = s0;
                    if (s1 < best[slot]) { best2[slot] = best[slot]; best[slot] = s1; bi[slot] = i1; }
                    else if (s1 < best2[slot]) best2[slot] = s1;
                }
            }
        }
        __syncthreads();  // protect B stage reuse
    }

    // quad reduce (lanes sharing the same rows: xor 1, 2)
#pragma unroll
    for (int o = 1; o < 4; o <<= 1) {
#pragma unroll
        for (int s = 0; s < 4; s++) {
            float ob = __shfl_xor_sync(0xffffffffu, best[s], o);
            float ob2 = __shfl_xor_sync(0xffffffffu, best2[s], o);
            int obi = __shfl_xor_sync(0xffffffffu, bi[s], o);
            if (ob < best[s] || (ob == best[s] && obi < bi[s])) {
                best2[s] = fminf(best[s], ob2);
                best[s] = ob;
                bi[s] = obi;
            } else {
                best2[s] = fminf(best2[s], ob);
            }
        }
    }
    if ((lane & 3) == 0) {
#pragma unroll
        for (int s = 0; s < 4; s++) {
            int row = wm * 32 + (s >> 1) * 16 + (lane >> 2) + (s & 1) * 8;
            s_b[wn][row] = best[s];
            s_b2[wn][row] = best2[s];
            s_i[wn][row] = bi[s];
        }
    }
    __syncthreads();
    if (tid < TILE_M) {
        float b0v = s_b[0][tid], b1v = s_b[1][tid];
        float q0 = s_b2[0][tid], q1 = s_b2[1][tid];
        int i0 = s_i[0][tid], i1 = s_i[1][tid];
        float nb, nb2;
        int ni;
        if (b0v < b1v || (b0v == b1v && i0 < i1)) {
            nb = b0v; ni = i0; nb2 = fminf(q0, b1v);
        } else {
            nb = b1v; ni = i1; nb2 = fminf(q1, b0v);
        }
        const int v = blockIdx.x * TILE_M + tid;
        g_bidx[v] = ni;
        if (nb2 - nb < TAU) {
            int p = atomicAdd(&g_count, 1);
            g_list[p] = v;
        }
    }
}

// ---------------- exact fp32 fixup for small-margin voxels ----------------
__global__ void __launch_bounds__(256) fixup_kernel(const float* __restrict__ z,
                                                    const float* __restrict__ emb) {
    const int nflag = g_count;
    const int gw = (blockIdx.x * blockDim.x + threadIdx.x) >> 5;
    const int lane = threadIdx.x & 31;
    const int nwarps = (gridDim.x * blockDim.x) >> 5;

    for (int i = gw; i < nflag; i += nwarps) {
        const int v = g_list[i];
        float4 zr[16];
        const float4* zp = reinterpret_cast<const float4*>(z + (size_t)v * DIM);
#pragma unroll
        for (int j = 0; j < 16; j++) zr[j] = zp[j];

        float lb = 3.4e38f;
        int li = 0;
        for (int c = lane; c < NC; c += 32) {
            const float4* ep = reinterpret_cast<const float4*>(emb + (size_t)c * DIM);
            float dot = 0.f;
#pragma unroll
            for (int j = 0; j < 16; j++) {
                float4 e = ep[j];
                dot = fmaf(zr[j].x, e.x, dot);
                dot = fmaf(zr[j].y, e.y, dot);
                dot = fmaf(zr[j].z, e.z, dot);
                dot = fmaf(zr[j].w, e.w, dot);
            }
            float s = fmaf(-2.f, dot, g_esq[c]);
            if (s < lb) { lb = s; li = c; }
        }
#pragma unroll
        for (int o = 16; o > 0; o >>= 1) {
            float os = __shfl_down_sync(0xffffffffu, lb, o);
            int oi = __shfl_down_sync(0xffffffffu, li, o);
            if (os < lb || (os == lb && oi < li)) { lb = os; li = oi; }
        }
        if (lane == 0) g_bidx[v] = li;
    }
}

// ---------------- gather / straight-through / loss partials ----------------
__global__ void __launch_bounds__(128) quant_kernel(const float* __restrict__ z,
                                                    const float* __restrict__ emb,
                                                    float* __restrict__ out) {
    __shared__ float s_red[128];
    const int v = blockIdx.x * 128 + threadIdx.x;
    const int idx = g_bidx[v];

    const float4* zp = reinterpret_cast<const float4*>(z + (size_t)v * DIM);
    const float4* qp = reinterpret_cast<const float4*>(emb + (size_t)idx * DIM);
    float4* qo = reinterpret_cast<float4*>(out + (size_t)v * DIM);
    float lsum = 0.f;
#pragma unroll
    for (int i = 0; i < 16; i++) {
        float4 zv = zp[i], q = qp[i];
        float dx = q.x - zv.x, dy = q.y - zv.y, dz = q.z - zv.z, dw = q.w - zv.w;
        qo[i] = make_float4(zv.x + dx, zv.y + dy, zv.z + dz, zv.w + dw);
        lsum += dx * dx + dy * dy + dz * dz + dw * dw;
    }
    out[OFF_IDX + v] = (float)idx;

    s_red[threadIdx.x] = lsum;
    __syncthreads();
#pragma unroll
    for (int o = 64; o > 0; o >>= 1) {
        if (threadIdx.x < o) s_red[threadIdx.x] += s_red[threadIdx.x + o];
        __syncthreads();
    }
    if (threadIdx.x == 0) g_partial[blockIdx.x] = s_red[0];
}

// ---------------- final loss reduction ----------------
__global__ void final_kernel(float* __restrict__ out) {
    __shared__ float s[M_BLOCKS];
    int tid = threadIdx.x;
    s[tid] = g_partial[tid];
    __syncthreads();
#pragma unroll
    for (int o = M_BLOCKS / 2; o > 0; o >>= 1) {
        if (tid < o) s[tid] += s[tid + o];
        __syncthreads();
    }
    if (tid == 0) {
        float loss = s[0] / (float)Q_ELEMS;
        out[OFF_VQ] = loss;
        out[OFF_COMMIT] = loss;
    }
}

// ---------------- launch ----------------
extern "C" void kernel_launch(void* const* d_in, const int* in_sizes, int n_in,
                              void* d_out, int out_size) {
    const float* z = (const float*)d_in[0];
    const float* emb = (const float*)d_in[1];
    if (n_in >= 2 && in_sizes[0] < in_sizes[1]) {
        const float* t = z; z = emb; emb = t;
    }
    float* out = (float*)d_out;

    static int attr_done = 0;
    if (!attr_done) {
        cudaFuncSetAttribute(vq_mma_kernel,
                             cudaFuncAttributeMaxDynamicSharedMemorySize, DYN_SMEM);
        attr_done = 1;
    }

    prep_emb_kernel<<<(NC + 255) / 256, 256>>>(emb);
    prep_z_kernel<<<(NV + 255) / 256, 256>>>(z);
    vq_mma_kernel<<<M_BLOCKS, 256, DYN_SMEM>>>();
    fixup_kernel<<<64, 256>>>(z, emb);
    quant_kernel<<<NV / 128, 128>>>(z, emb, out);
    final_kernel<<<1, M_BLOCKS>>>(out);
}

// round 4
// speedup vs baseline: 1.4561x; 1.1600x over previous
#include <cuda_runtime.h>
#include <cuda_fp16.h>
#include <cstdint>

// ---------------- problem constants ----------------
#define NV 32768
#define NC 8192
#define DIM 64
#define Q_ELEMS (NV * DIM)
#define OFF_VQ Q_ELEMS
#define OFF_COMMIT (Q_ELEMS + 1)
#define OFF_IDX (Q_ELEMS + 2)

#define KC 192          // concatenated K: [zh|zh|zl] x [eh|el|eh]
#define KP_BYTES 400    // padded smem row stride (25 x 16B, conflict-free)
#define TILE_M 128
#define TILE_N 64
#define NT (NC / TILE_N)        // 128 tiles
#define M_BLOCKS (NV / TILE_M)  // 256 CTAs
#define TAU 2e-3f

// dynamic smem: A 128*400=51200 | B stage0 64*400=25600 | B stage1 | esq 2*256
#define SM_A 0
#define SM_B 51200
#define SM_BSTRIDE 25600
#define SM_ESQ 102400
#define DYN_SMEM 102912

// ---------------- device scratch ----------------
__device__ __align__(16) __half g_zcat[NV * KC];   // 12 MB
__device__ __align__(16) __half g_ecat[NC * KC];   // 3 MB
__device__ __align__(16) float g_esq[NC];
__device__ int g_bidx[NV];
__device__ int g_list[NV];
__device__ int g_count;
__device__ float g_partial[M_BLOCKS];

// ---------------- PTX helpers (baseline sm_80+ features only) ----------------
__device__ __forceinline__ uint32_t smem_u32(const void* p) {
    uint32_t a;
    asm("{ .reg .u64 t; cvta.to.shared.u64 t, %1; cvt.u32.u64 %0, t; }" : "=r"(a) : "l"(p));
    return a;
}
__device__ __forceinline__ void cpa16(uint32_t dst, const void* src) {
    asm volatile("cp.async.cg.shared.global [%0], [%1], 16;" :: "r"(dst), "l"(src));
}
#define CP_COMMIT() asm volatile("cp.async.commit_group;" ::: "memory")
#define CP_WAIT(n) asm volatile("cp.async.wait_group %0;" :: "n"(n) : "memory")

__device__ __forceinline__ void ldsm4(uint32_t& r0, uint32_t& r1, uint32_t& r2,
                                      uint32_t& r3, uint32_t addr) {
    asm volatile("ldmatrix.sync.aligned.m8n8.x4.shared.b16 {%0,%1,%2,%3}, [%4];"
                 : "=r"(r0), "=r"(r1), "=r"(r2), "=r"(r3) : "r"(addr));
}
__device__ __forceinline__ void mma16816(float* c, const uint32_t* a, uint32_t b0,
                                         uint32_t b1) {
    asm volatile(
        "mma.sync.aligned.m16n8k16.row.col.f32.f16.f16.f32 "
        "{%0,%1,%2,%3}, {%4,%5,%6,%7}, {%8,%9}, {%0,%1,%2,%3};"
        : "+f"(c[0]), "+f"(c[1]), "+f"(c[2]), "+f"(c[3])
        : "r"(a[0]), "r"(a[1]), "r"(a[2]), "r"(a[3]), "r"(b0), "r"(b1));
}

// ---------------- prep: codebook -> fp16 split concat + exact esq ----------------
__global__ void prep_emb_kernel(const float* __restrict__ emb) {
    int c = blockIdx.x * blockDim.x + threadIdx.x;
    if (c == 0) g_count = 0;
    if (c >= NC) return;
    const float4* row = reinterpret_cast<const float4*>(emb + (size_t)c * DIM);
    __half2* dst = reinterpret_cast<__half2*>(g_ecat + (size_t)c * KC);
    float s = 0.f;
#pragma unroll
    for (int i = 0; i < 16; i++) {
        float4 v = row[i];
        s += v.x * v.x + v.y * v.y + v.z * v.z + v.w * v.w;
        __half hx = __float2half_rn(v.x), hy = __float2half_rn(v.y);
        __half hz = __float2half_rn(v.z), hw = __float2half_rn(v.w);
        __half2 h0 = __halves2half2(hx, hy), h1 = __halves2half2(hz, hw);
        __half2 l0 = __halves2half2(__float2half_rn(v.x - __half2float(hx)),
                                    __float2half_rn(v.y - __half2float(hy)));
        __half2 l1 = __halves2half2(__float2half_rn(v.z - __half2float(hz)),
                                    __float2half_rn(v.w - __half2float(hw)));
        dst[2 * i] = h0;                 // eh   cols [0,64)
        dst[2 * i + 1] = h1;
        dst[32 + 2 * i] = l0;            // el   cols [64,128)
        dst[32 + 2 * i + 1] = l1;
        dst[64 + 2 * i] = h0;            // eh   cols [128,192)
        dst[64 + 2 * i + 1] = h1;
    }
    g_esq[c] = s;
}

// ---------------- prep: z -> fp16 split concat ----------------
__global__ void prep_z_kernel(const float* __restrict__ z) {
    int v = blockIdx.x * blockDim.x + threadIdx.x;
    if (v >= NV) return;
    const float4* row = reinterpret_cast<const float4*>(z + (size_t)v * DIM);
    __half2* dst = reinterpret_cast<__half2*>(g_zcat + (size_t)v * KC);
#pragma unroll
    for (int i = 0; i < 16; i++) {
        float4 vv = row[i];
        __half hx = __float2half_rn(vv.x), hy = __float2half_rn(vv.y);
        __half hz = __float2half_rn(vv.z), hw = __float2half_rn(vv.w);
        __half2 h0 = __halves2half2(hx, hy), h1 = __halves2half2(hz, hw);
        __half2 l0 = __halves2half2(__float2half_rn(vv.x - __half2float(hx)),
                                    __float2half_rn(vv.y - __half2float(hy)));
        __half2 l1 = __halves2half2(__float2half_rn(vv.z - __half2float(hz)),
                                    __float2half_rn(vv.w - __half2float(hw)));
        dst[2 * i] = h0;                 // zh
        dst[2 * i + 1] = h1;
        dst[32 + 2 * i] = h0;            // zh (paired with el)
        dst[32 + 2 * i + 1] = h1;
        dst[64 + 2 * i] = l0;            // zl (paired with eh)
        dst[64 + 2 * i + 1] = l1;
    }
}

// ---------------- main: HMMA distance GEMM + approx argmin ----------------
__global__ void __launch_bounds__(256, 2) vq_mma_kernel() {
    extern __shared__ __align__(16) char dsm[];
    __shared__ float s_b[2][TILE_M], s_b2[2][TILE_M];
    __shared__ int s_i[2][TILE_M];

    const int tid = threadIdx.x;
    const int lane = tid & 31, wid = tid >> 5;
    const int wm = wid & 3, wn = wid >> 2;  // 4 M-stripes x 2 N-stripes
    const uint32_t sb = smem_u32(dsm);

    // A tile: 128 rows x 192 halfs (384B) -> padded 400B rows
    {
        const uint4* asrc =
            reinterpret_cast<const uint4*>(g_zcat + (size_t)blockIdx.x * TILE_M * KC);
#pragma unroll
        for (int i = 0; i < 12; i++) {
            int ch = tid + i * 256;              // 3072 chunks of 16B
            int r = ch / 24, c = ch % 24;
            cpa16(sb + SM_A + r * KP_BYTES + c * 16, asrc + ch);
        }
    }
    auto loadB = [&](int t) {
        uint32_t Bs = sb + SM_B + (t & 1) * SM_BSTRIDE;
        const uint4* bsrc =
            reinterpret_cast<const uint4*>(g_ecat + (size_t)t * TILE_N * KC);
#pragma unroll
        for (int i = 0; i < 6; i++) {
            int ch = tid + i * 256;              // 1536 chunks
            int r = ch / 24, c = ch % 24;
            cpa16(Bs + r * KP_BYTES + c * 16, bsrc + ch);
        }
        if (tid < 16)
            cpa16(sb + SM_ESQ + (t & 1) * 256 + tid * 16,
                  reinterpret_cast<const uint4*>(g_esq + t * TILE_N) + tid);
    };
    loadB(0);
    CP_COMMIT();

    float best[4], best2[4];
    int bi[4];
#pragma unroll
    for (int s = 0; s < 4; s++) { best[s] = 3.4e38f; best2[s] = 3.4e38f; bi[s] = 0; }

    const uint32_t a_row = wm * 32 + (lane & 15);
    const uint32_t a_koff = (lane >> 4) * 8;
    const uint32_t b_row0 = wn * 32 + ((lane >> 4) * 8) + (lane & 7);
    const uint32_t b_koff = ((lane >> 3) & 1) * 8;
    const int nq = (lane & 3) * 2;

    for (int t = 0; t < NT; t++) {
        if (t + 1 < NT) { loadB(t + 1); CP_COMMIT(); CP_WAIT(1); }
        else           { CP_WAIT(0); }
        __syncthreads();

        float acc[2][4][4];
#pragma unroll
        for (int mf = 0; mf < 2; mf++)
#pragma unroll
            for (int nf = 0; nf < 4; nf++)
#pragma unroll
                for (int e = 0; e < 4; e++) acc[mf][nf][e] = 0.f;

        const uint32_t Bs = sb + SM_B + (t & 1) * SM_BSTRIDE;
#pragma unroll
        for (int ks = 0; ks < KC / 16; ks++) {
            uint32_t a[2][4];
#pragma unroll
            for (int mf = 0; mf < 2; mf++)
                ldsm4(a[mf][0], a[mf][1], a[mf][2], a[mf][3],
                      sb + SM_A + (a_row + mf * 16) * KP_BYTES +
                          (ks * 16 + a_koff) * 2);
            uint32_t b[4][2];
#pragma unroll
            for (int nh = 0; nh < 2; nh++)
                ldsm4(b[2 * nh][0], b[2 * nh][1], b[2 * nh + 1][0], b[2 * nh + 1][1],
                      Bs + (b_row0 + nh * 16) * KP_BYTES + (ks * 16 + b_koff) * 2);
#pragma unroll
            for (int mf = 0; mf < 2; mf++)
#pragma unroll
                for (int nf = 0; nf < 4; nf++)
                    mma16816(acc[mf][nf], a[mf], b[nf][0], b[nf][1]);
        }

        // epilogue: scores into regs per row-slot, fast tree-min skip path
        const float* esq =
            reinterpret_cast<const float*>(dsm + SM_ESQ + (t & 1) * 256);
        float sc[4][8];  // [slot = mf*2+h][nf*2 + colpair]
#pragma unroll
        for (int mf = 0; mf < 2; mf++) {
#pragma unroll
            for (int nf = 0; nf < 4; nf++) {
                const int n0 = wn * 32 + nf * 8 + nq;
                const float e0 = esq[n0], e1 = esq[n0 + 1];
#pragma unroll
                for (int h = 0; h < 2; h++) {
                    sc[mf * 2 + h][nf * 2 + 0] = fmaf(-2.f, acc[mf][nf][2 * h], e0);
                    sc[mf * 2 + h][nf * 2 + 1] = fmaf(-2.f, acc[mf][nf][2 * h + 1], e1);
                }
            }
        }
#pragma unroll
        for (int s = 0; s < 4; s++) {
            float m01 = fminf(sc[s][0], sc[s][1]);
            float m23 = fminf(sc[s][2], sc[s][3]);
            float m45 = fminf(sc[s][4], sc[s][5]);
            float m67 = fminf(sc[s][6], sc[s][7]);
            float tmin = fminf(fminf(m01, m23), fminf(m45, m67));
            if (tmin < best2[s]) {  // rare after the first few tiles
#pragma unroll
                for (int k = 0; k < 8; k++) {
                    float v = sc[s][k];
                    int idx = t * TILE_N + wn * 32 + (k >> 1) * 8 + nq + (k & 1);
                    if (v < best[s]) { best2[s] = best[s]; best[s] = v; bi[s] = idx; }
                    else if (v < best2[s]) best2[s] = v;
                }
            }
        }
        __syncthreads();  // protect B stage reuse
    }

    // quad reduce (lanes sharing the same rows: xor 1, 2)
#pragma unroll
    for (int o = 1; o < 4; o <<= 1) {
#pragma unroll
        for (int s = 0; s < 4; s++) {
            float ob = __shfl_xor_sync(0xffffffffu, best[s], o);
            float ob2 = __shfl_xor_sync(0xffffffffu, best2[s], o);
            int obi = __shfl_xor_sync(0xffffffffu, bi[s], o);
            if (ob < best[s] || (ob == best[s] && obi < bi[s])) {
                best2[s] = fminf(best[s], ob2);
                best[s] = ob;
                bi[s] = obi;
            } else {
                best2[s] = fminf(best2[s], ob);
            }
        }
    }
    if ((lane & 3) == 0) {
#pragma unroll
        for (int s = 0; s < 4; s++) {
            int row = wm * 32 + (s >> 1) * 16 + (lane >> 2) + (s & 1) * 8;
            s_b[wn][row] = best[s];
            s_b2[wn][row] = best2[s];
            s_i[wn][row] = bi[s];
        }
    }
    __syncthreads();
    if (tid < TILE_M) {
        float b0v = s_b[0][tid], b1v = s_b[1][tid];
        float q0 = s_b2[0][tid], q1 = s_b2[1][tid];
        int i0 = s_i[0][tid], i1 = s_i[1][tid];
        float nb, nb2;
        int ni;
        if (b0v < b1v || (b0v == b1v && i0 < i1)) {
            nb = b0v; ni = i0; nb2 = fminf(q0, b1v);
        } else {
            nb = b1v; ni = i1; nb2 = fminf(q1, b0v);
        }
        const int v = blockIdx.x * TILE_M + tid;
        g_bidx[v] = ni;
        if (nb2 - nb < TAU) {
            int p = atomicAdd(&g_count, 1);
            g_list[p] = v;
        }
    }
}

// ---------------- exact fp32 fixup: block-per-voxel ----------------
__global__ void __launch_bounds__(256) fixup_kernel(const float* __restrict__ z,
                                                    const float* __restrict__ emb) {
    __shared__ float s_z[DIM];
    __shared__ float s_v[256];
    __shared__ int s_ix[256];
    const int tid = threadIdx.x;
    const int nflag = g_count;

    for (int i = blockIdx.x; i < nflag; i += gridDim.x) {
        const int v = g_list[i];
        if (tid < 16)
            reinterpret_cast<float4*>(s_z)[tid] =
                reinterpret_cast<const float4*>(z + (size_t)v * DIM)[tid];
        __syncthreads();

        float lb = 3.4e38f;
        int li = 0;
        // 32 codes per thread, strided; 4 independent FMA chains; unroll 2 for MLP
#pragma unroll 2
        for (int c = tid; c < NC; c += 256) {
            const float4* ep = reinterpret_cast<const float4*>(emb + (size_t)c * DIM);
            float d0 = 0.f, d1 = 0.f, d2 = 0.f, d3 = 0.f;
#pragma unroll
            for (int j = 0; j < 16; j += 4) {
                float4 e0 = ep[j], e1 = ep[j + 1], e2 = ep[j + 2], e3 = ep[j + 3];
                d0 = fmaf(s_z[4 * j + 0], e0.x, d0);
                d0 = fmaf(s_z[4 * j + 1], e0.y, d0);
                d0 = fmaf(s_z[4 * j + 2], e0.z, d0);
                d0 = fmaf(s_z[4 * j + 3], e0.w, d0);
                d1 = fmaf(s_z[4 * j + 4], e1.x, d1);
                d1 = fmaf(s_z[4 * j + 5], e1.y, d1);
                d1 = fmaf(s_z[4 * j + 6], e1.z, d1);
                d1 = fmaf(s_z[4 * j + 7], e1.w, d1);
                d2 = fmaf(s_z[4 * j + 8], e2.x, d2);
                d2 = fmaf(s_z[4 * j + 9], e2.y, d2);
                d2 = fmaf(s_z[4 * j + 10], e2.z, d2);
                d2 = fmaf(s_z[4 * j + 11], e2.w, d2);
                d3 = fmaf(s_z[4 * j + 12], e3.x, d3);
                d3 = fmaf(s_z[4 * j + 13], e3.y, d3);
                d3 = fmaf(s_z[4 * j + 14], e3.z, d3);
                d3 = fmaf(s_z[4 * j + 15], e3.w, d3);
            }
            float dot = (d0 + d1) + (d2 + d3);
            float s = fmaf(-2.f, dot, g_esq[c]);
            if (s < lb) { lb = s; li = c; }  // ascending c => lowest index on tie
        }
        s_v[tid] = lb;
        s_ix[tid] = li;
        __syncthreads();
#pragma unroll
        for (int o = 128; o > 0; o >>= 1) {
            if (tid < o) {
                float ov = s_v[tid + o];
                int oi = s_ix[tid + o];
                if (ov < s_v[tid] || (ov == s_v[tid] && oi < s_ix[tid])) {
                    s_v[tid] = ov;
                    s_ix[tid] = oi;
                }
            }
            __syncthreads();
        }
        if (tid == 0) g_bidx[v] = s_ix[0];
        __syncthreads();  // s_z reuse next iteration
    }
}

// ---------------- gather / straight-through / loss partials ----------------
__global__ void __launch_bounds__(128) quant_kernel(const float* __restrict__ z,
                                                    const float* __restrict__ emb,
                                                    float* __restrict__ out) {
    __shared__ float s_red[128];
    const int v = blockIdx.x * 128 + threadIdx.x;
    const int idx = g_bidx[v];

    const float4* zp = reinterpret_cast<const float4*>(z + (size_t)v * DIM);
    const float4* qp = reinterpret_cast<const float4*>(emb + (size_t)idx * DIM);
    float4* qo = reinterpret_cast<float4*>(out + (size_t)v * DIM);
    float lsum = 0.f;
#pragma unroll
    for (int i = 0; i < 16; i++) {
        float4 zv = zp[i], q = qp[i];
        float dx = q.x - zv.x, dy = q.y - zv.y, dz = q.z - zv.z, dw = q.w - zv.w;
        qo[i] = make_float4(zv.x + dx, zv.y + dy, zv.z + dz, zv.w + dw);
        lsum += dx * dx + dy * dy + dz * dz + dw * dw;
    }
    out[OFF_IDX + v] = (float)idx;

    s_red[threadIdx.x] = lsum;
    __syncthreads();
#pragma unroll
    for (int o = 64; o > 0; o >>= 1) {
        if (threadIdx.x < o) s_red[threadIdx.x] += s_red[threadIdx.x + o];
        __syncthreads();
    }
    if (threadIdx.x == 0) g_partial[blockIdx.x] = s_red[0];
}

// ---------------- final loss reduction ----------------
__global__ void final_kernel(float* __restrict__ out) {
    __shared__ float s[M_BLOCKS];
    int tid = threadIdx.x;
    s[tid] = g_partial[tid];
    __syncthreads();
#pragma unroll
    for (int o = M_BLOCKS / 2; o > 0; o >>= 1) {
        if (tid < o) s[tid] += s[tid + o];
        __syncthreads();
    }
    if (tid == 0) {
        float loss = s[0] / (float)Q_ELEMS;
        out[OFF_VQ] = loss;
        out[OFF_COMMIT] = loss;
    }
}

// ---------------- launch ----------------
extern "C" void kernel_launch(void* const* d_in, const int* in_sizes, int n_in,
                              void* d_out, int out_size) {
    const float* z = (const float*)d_in[0];
    const float* emb = (const float*)d_in[1];
    if (n_in >= 2 && in_sizes[0] < in_sizes[1]) {
        const float* t = z; z = emb; emb = t;
    }
    float* out = (float*)d_out;

    cudaFuncSetAttribute(vq_mma_kernel,
                         cudaFuncAttributeMaxDynamicSharedMemorySize, DYN_SMEM);

    prep_emb_kernel<<<(NC + 255) / 256, 256>>>(emb);
    prep_z_kernel<<<(NV + 255) / 256, 256>>>(z);
    vq_mma_kernel<<<M_BLOCKS, 256, DYN_SMEM>>>();
    fixup_kernel<<<2048, 256>>>(z, emb);
    quant_kernel<<<NV / 128, 128>>>(z, emb, out);
    final_kernel<<<1, M_BLOCKS>>>(out);
}